// round 12
// baseline (speedup 1.0000x reference)
#include <cuda_runtime.h>
#include <cuda_fp16.h>
#include <cstdint>
#include <cstddef>

// ---------------- problem constants ----------------
#define B_DIM   8192
#define H_DIM   1024
#define NC_DIM  16
#define KTOT    2048          // IN + H

// ---------------- tile config ----------------
#define BM      128
#define BN      64            // 4 gates x 16 (gate-interleaved)
#define BK      128           // 128 fp16 = two 128B column-blocks
#define STAGES  2
#define NKIT    (KTOT / BK)   // 16
#define NTHREADS 128          // 4 warps, warp tile 64x32

// SMEM layout
#define SM_TILES   1024                          // stage buffers start
#define SA_BLK     16384                         // one 128-col block of A (128 rows x 128B)
#define SA_BYTES   (2 * SA_BLK)                  // 32768
#define SB_BLK     8192                          // one block of B (64 rows x 128B)
#define SB_BYTES   (2 * SB_BLK)                  // 16384
#define SSTRIDE    (SA_BYTES + SB_BYTES)         // 49152
#define SMEM_BYTES (SM_TILES + STAGES * SSTRIDE) // 99328 (x2 CTAs = 198656 <= 227KB)

#define EPI_PITCH  68                            // fp32 epilogue staging pitch (mult of 4)

// ---------------- device scratch ----------------
__device__ __align__(16) __half g_A[(size_t)B_DIM * KTOT];      // [x | hx]
__device__ __align__(16) __half g_B[(size_t)4 * H_DIM * KTOT];  // [W_ih | W_hh]
__device__ float g_cin[B_DIM * NC_DIM];
__device__ float g_cfg[B_DIM * NC_DIM];

// ---------------- helpers ----------------
__device__ __forceinline__ uint32_t smem_u32(const void* p) {
    uint32_t a;
    asm("{ .reg .u64 t; cvta.to.shared.u64 t, %1; cvt.u32.u64 %0, t; }" : "=r"(a) : "l"(p));
    return a;
}

__device__ __forceinline__ uint32_t sw128(uint32_t off) { return off ^ ((off >> 3) & 0x70); }

__device__ __forceinline__ void cp_async16(uint32_t dst, const void* src) {
    asm volatile("cp.async.cg.shared.global [%0], [%1], 16;" :: "r"(dst), "l"(src) : "memory");
}
#define CP_COMMIT() asm volatile("cp.async.commit_group;" ::: "memory")
#define CP_WAIT(N)  asm volatile("cp.async.wait_group %0;" :: "n"(N) : "memory")

__device__ __forceinline__ void ldsm4(uint32_t* r, uint32_t addr) {
    asm volatile("ldmatrix.sync.aligned.m8n8.x4.shared.b16 {%0,%1,%2,%3}, [%4];"
                 : "=r"(r[0]), "=r"(r[1]), "=r"(r[2]), "=r"(r[3]) : "r"(addr));
}

__device__ __forceinline__ void mma16816(float* d, const uint32_t* a, const uint32_t* b) {
    asm volatile("mma.sync.aligned.m16n8k16.row.col.f32.f16.f16.f32 "
                 "{%0,%1,%2,%3}, {%4,%5,%6,%7}, {%8,%9}, {%0,%1,%2,%3};"
                 : "+f"(d[0]), "+f"(d[1]), "+f"(d[2]), "+f"(d[3])
                 : "r"(a[0]), "r"(a[1]), "r"(a[2]), "r"(a[3]), "r"(b[0]), "r"(b[1]));
}

__device__ __forceinline__ float sigmoidf_(float x) { return 1.0f / (1.0f + __expf(-x)); }

// ---------------- conversion kernels ----------------
__global__ void convA_kernel(const float* __restrict__ x, const float* __restrict__ hx) {
    size_t i = ((size_t)blockIdx.x * blockDim.x + threadIdx.x) * 8;
    int b = (int)(i >> 11);
    int k = (int)(i & 2047);
    const float* src = (k < 1024) ? (x + (size_t)b * 1024 + k)
                                  : (hx + (size_t)b * 1024 + (k - 1024));
    float4 f0 = *(const float4*)src;
    float4 f1 = *(const float4*)(src + 4);
    __half2 h[4];
    h[0] = __floats2half2_rn(f0.x, f0.y);
    h[1] = __floats2half2_rn(f0.z, f0.w);
    h[2] = __floats2half2_rn(f1.x, f1.y);
    h[3] = __floats2half2_rn(f1.z, f1.w);
    *(uint4*)(g_A + i) = *(uint4*)h;
}

__global__ void convB_kernel(const float* __restrict__ Wih, const float* __restrict__ Whh) {
    size_t i = ((size_t)blockIdx.x * blockDim.x + threadIdx.x) * 8;
    int g = (int)(i >> 11);
    int k = (int)(i & 2047);
    const float* src = (k < 1024) ? (Wih + (size_t)g * 1024 + k)
                                  : (Whh + (size_t)g * 1024 + (k - 1024));
    float4 f0 = *(const float4*)src;
    float4 f1 = *(const float4*)(src + 4);
    __half2 h[4];
    h[0] = __floats2half2_rn(f0.x, f0.y);
    h[1] = __floats2half2_rn(f0.z, f0.w);
    h[2] = __floats2half2_rn(f1.x, f1.y);
    h[3] = __floats2half2_rn(f1.z, f1.w);
    *(uint4*)(g_B + i) = *(uint4*)h;
}

// ---------------- cumsoftmax floors ----------------
__global__ void floors_kernel(const float* __restrict__ ifl, const float* __restrict__ ffl) {
    int b = blockIdx.x * blockDim.x + threadIdx.x;
    if (b >= B_DIM) return;
    float v[16], w[16];
#pragma unroll
    for (int i = 0; i < 16; i++) { v[i] = ifl[b * 16 + i]; w[i] = ffl[b * 16 + i]; }
#pragma unroll
    for (int h = 0; h < 4; h++) {
        float* a = (h < 2) ? (v + 8 * h) : (w + 8 * (h - 2));
        float m = a[0];
#pragma unroll
        for (int i = 1; i < 8; i++) m = fmaxf(m, a[i]);
        float s = 0.f;
#pragma unroll
        for (int i = 0; i < 8; i++) { a[i] = expf(a[i] - m); s += a[i]; }
        float inv = 1.0f / s;
#pragma unroll
        for (int i = 0; i < 8; i++) a[i] *= inv;
    }
    float* cin = g_cin + (size_t)b * 16;
    float* cfg = g_cfg + (size_t)b * 16;
    float run;
    run = 0.f;
#pragma unroll
    for (int i = 0; i < 8; i++) { run += v[i]; cin[i] = run; }          // happy in: prefix
    run = 0.f;
#pragma unroll
    for (int i = 7; i >= 0; i--) { run += v[8 + i]; cin[8 + i] = run; } // sad in: suffix
    run = 0.f;
#pragma unroll
    for (int i = 7; i >= 0; i--) { run += w[i]; cfg[i] = run; }         // happy fg: suffix
    run = 0.f;
#pragma unroll
    for (int i = 0; i < 8; i++) { run += w[8 + i]; cfg[8 + i] = run; }  // sad fg: prefix
}

// ---------------- stage loaders ----------------
// One stage = 3072 16B chunks (A: 2048, B: 1024). Split into 8 parts of 384
// (3 chunks/thread) so load issuance trickles under the MMA stream.
__device__ __forceinline__ void load_chunks(uint32_t sb, int k0, int buf, int j, int m0,
                                            int tid, int part) {
    const uint32_t ab = sb + SM_TILES + buf * SSTRIDE;
    const uint32_t bb = ab + SA_BYTES;
#pragma unroll
    for (int i = 0; i < 3; i++) {
        int idx = tid + (part * 3 + i) * NTHREADS;   // 0..3071
        if (idx < 2048) {                            // A: 2 blocks x 128 rows x 8 chunks
            int b2 = idx >> 10;
            int rem = idx & 1023;
            int r = rem >> 3, c = rem & 7;
            const __half* src = g_A + (size_t)(m0 + r) * KTOT + k0 + b2 * 64 + c * 8;
            cp_async16(ab + b2 * SA_BLK + sw128((uint32_t)(r * 128 + c * 16)), src);
        } else {                                     // B: 2 blocks x 64 rows x 8 chunks
            int v = idx - 2048;
            int b2 = v >> 9;
            int rem = v & 511;
            int r = rem >> 3, c = rem & 7;
            int grow = (r >> 4) * 1024 + j * 16 + (r & 15);   // gate-interleaved 4x16
            const __half* src = g_B + (size_t)grow * KTOT + k0 + b2 * 64 + c * 8;
            cp_async16(bb + b2 * SB_BLK + sw128((uint32_t)(r * 128 + c * 16)), src);
        }
    }
}

// ---------------- fragment loader (one k16 step ks in 0..7) ----------------
__device__ __forceinline__ void load_frags(
    uint32_t ab, uint32_t bb, int wm, int wn, int lane, int ks,
    uint32_t af[4][4], uint32_t bf[2][4])
{
    const int kb = ks >> 2;                 // 128B column block
    const int kq = ks & 3;                  // k16 within block
#pragma unroll
    for (int i = 0; i < 4; i++) {
        int m  = wm * 64 + i * 16 + (lane & 15);
        int kc = kq * 2 + (lane >> 4);
        ldsm4(af[i], ab + kb * SA_BLK + sw128((uint32_t)(m * 128 + kc * 16)));
    }
#pragma unroll
    for (int p = 0; p < 2; p++) {
        int n  = wn * 32 + p * 16 + ((lane >> 4) & 1) * 8 + (lane & 7);
        int kc = kq * 2 + ((lane >> 3) & 1);
        ldsm4(bf[p], bb + kb * SB_BLK + sw128((uint32_t)(n * 128 + kc * 16)));
    }
}

// ---------------- fused GEMM + ONLSTM epilogue ----------------
__global__ void __launch_bounds__(NTHREADS, 2)
onlstm_kernel(const float* __restrict__ cx,
              const float* __restrict__ bih, const float* __restrict__ bhh,
              float* __restrict__ out_hy, float* __restrict__ out_cy)
{
    extern __shared__ char smem[];
    const int tid = threadIdx.x;
    const int wid = tid >> 5, lane = tid & 31;
    const int j  = blockIdx.x;          // 16-column tile index 0..63
    const int m0 = blockIdx.y * BM;     // batch-row base
    const uint32_t sb = smem_u32(smem);

    float* sbias = (float*)smem;        // 64 floats, region [0,1024)
    if (tid < 64) {
        int grow = (tid >> 4) * 1024 + j * 16 + (tid & 15);
        sbias[tid] = bih[grow] + bhh[grow];
    }

    // prologue: fully prefetch stage 0
#pragma unroll
    for (int p = 0; p < 8; p++) load_chunks(sb, 0, 0, j, m0, tid, p);
    CP_COMMIT();

    const int wm = wid >> 1;            // 0..1  (M)
    const int wn = wid & 1;             // 0..1  (N)

    float acc[4][4][4];                 // 64x32 warp tile: 4 m16 x 4 n8
#pragma unroll
    for (int i = 0; i < 4; i++)
#pragma unroll
        for (int jn = 0; jn < 4; jn++)
#pragma unroll
            for (int t = 0; t < 4; t++) acc[i][jn][t] = 0.f;

    uint32_t af[2][4][4], bf[2][2][4];  // double-buffered fragments

    int buf = 0;
    for (int s = 0; s < NKIT; s++) {
        CP_WAIT(0);                     // stage s landed
        __syncthreads();                // all warps done with buf^1

        const uint32_t ab = sb + SM_TILES + buf * SSTRIDE;
        const uint32_t bb = ab + SA_BYTES;
        const bool more = (s + 1 < NKIT);
        const int nk0 = (s + 1) * BK;

        load_frags(ab, bb, wm, wn, lane, 0, af[0], bf[0]);

#pragma unroll
        for (int ks = 0; ks < 8; ks++) {        // 8 x k16 steps per stage
            const int cur = ks & 1;
            if (ks < 7)                         // prefetch next k16 fragments
                load_frags(ab, bb, wm, wn, lane, ks + 1, af[cur ^ 1], bf[cur ^ 1]);
            if (more)                           // trickle next-stage gmem loads
                load_chunks(sb, nk0, buf ^ 1, j, m0, tid, ks);
#pragma unroll
            for (int i = 0; i < 4; i++)
#pragma unroll
                for (int jn = 0; jn < 4; jn++)
                    mma16816(acc[i][jn], af[cur][i], &bf[cur][jn >> 1][(jn & 1) * 2]);
        }

        CP_COMMIT();
        buf ^= 1;
    }

    __syncthreads();

    // stage accumulators (raw gates, no bias yet) into SMEM, overlaying tile buffers
    float* epi = (float*)(smem + SM_TILES);
#pragma unroll
    for (int i = 0; i < 4; i++) {
#pragma unroll
        for (int jn = 0; jn < 4; jn++) {
            int r = wm * 64 + i * 16 + (lane >> 2);
            int c = wn * 32 + jn * 8 + (lane & 3) * 2;
            *(float2*)&epi[r * EPI_PITCH + c]       = make_float2(acc[i][jn][0], acc[i][jn][1]);
            *(float2*)&epi[(r + 8) * EPI_PITCH + c] = make_float2(acc[i][jn][2], acc[i][jn][3]);
        }
    }
    __syncthreads();

    // fused ONLSTM epilogue: this CTA owns gate columns [j*16, j*16+16) of each gate.
    // 128 rows x 16 cols = 2048 floats = 512 float4 groups; 4 groups per row.
    const int nc = j >> 2;              // head-chunk index (16-col tile -> 64-col chunk)
#pragma unroll
    for (int t = 0; t < 4; t++) {
        int idx = tid + t * NTHREADS;      // 0..511
        int r = idx >> 2;                  // 0..127
        int c4 = (idx & 3) * 4;            // 0,4,8,12
        int b = m0 + r;
        float ci = g_cin[b * 16 + nc];
        float cf = g_cfg[b * 16 + nc];
        float ov = cf * ci;
        float fa = cf - ov, ia = ci - ov;
        float4 go = *(float4*)&epi[r * EPI_PITCH + c4];
        float4 gc = *(float4*)&epi[r * EPI_PITCH + 16 + c4];
        float4 gi = *(float4*)&epi[r * EPI_PITCH + 32 + c4];
        float4 gf = *(float4*)&epi[r * EPI_PITCH + 48 + c4];
        size_t g = (size_t)b * H_DIM + j * 16 + c4;
        float4 cxv = *(const float4*)&cx[g];
        float4 hyv, cyv;
        {
            float o  = sigmoidf_(go.x + sbias[c4]);
            float ce = tanhf    (gc.x + sbias[16 + c4]);
            float ig = sigmoidf_(gi.x + sbias[32 + c4]) * ov + ia;
            float fg = sigmoidf_(gf.x + sbias[48 + c4]) * ov + fa;
            cyv.x = fg * cxv.x + ig * ce; hyv.x = o * tanhf(cyv.x);
        }
        {
            float o  = sigmoidf_(go.y + sbias[c4 + 1]);
            float ce = tanhf    (gc.y + sbias[17 + c4]);
            float ig = sigmoidf_(gi.y + sbias[33 + c4]) * ov + ia;
            float fg = sigmoidf_(gf.y + sbias[49 + c4]) * ov + fa;
            cyv.y = fg * cxv.y + ig * ce; hyv.y = o * tanhf(cyv.y);
        }
        {
            float o  = sigmoidf_(go.z + sbias[c4 + 2]);
            float ce = tanhf    (gc.z + sbias[18 + c4]);
            float ig = sigmoidf_(gi.z + sbias[34 + c4]) * ov + ia;
            float fg = sigmoidf_(gf.z + sbias[50 + c4]) * ov + fa;
            cyv.z = fg * cxv.z + ig * ce; hyv.z = o * tanhf(cyv.z);
        }
        {
            float o  = sigmoidf_(go.w + sbias[c4 + 3]);
            float ce = tanhf    (gc.w + sbias[19 + c4]);
            float ig = sigmoidf_(gi.w + sbias[35 + c4]) * ov + ia;
            float fg = sigmoidf_(gf.w + sbias[51 + c4]) * ov + fa;
            cyv.w = fg * cxv.w + ig * ce; hyv.w = o * tanhf(cyv.w);
        }
        *(float4*)&out_hy[g] = hyv;
        if (out_cy) *(float4*)&out_cy[g] = cyv;
    }
}

// ---------------- launch ----------------
extern "C" void kernel_launch(void* const* d_in, const int* in_sizes, int n_in,
                              void* d_out, int out_size) {
    const float* x   = (const float*)d_in[0];
    const float* hx  = (const float*)d_in[1];
    const float* cx  = (const float*)d_in[2];
    const float* ifl = (const float*)d_in[3];
    const float* ffl = (const float*)d_in[4];
    const float* Wih = (const float*)d_in[5];
    const float* bih = (const float*)d_in[6];
    const float* Whh = (const float*)d_in[7];
    const float* bhh = (const float*)d_in[8];

    float* out = (float*)d_out;
    float* out_hy = out;
    float* out_cy = ((long long)out_size >= 2LL * B_DIM * H_DIM)
                        ? out + (size_t)B_DIM * H_DIM : nullptr;

    convA_kernel<<<(B_DIM * (size_t)KTOT / 8 + 255) / 256, 256>>>(x, hx);
    convB_kernel<<<(4 * (size_t)H_DIM * KTOT / 8 + 255) / 256, 256>>>(Wih, Whh);
    floors_kernel<<<B_DIM / 256, 256>>>(ifl, ffl);

    cudaFuncSetAttribute(onlstm_kernel,
                         cudaFuncAttributeMaxDynamicSharedMemorySize, SMEM_BYTES);

    dim3 grid(H_DIM / 16, B_DIM / BM);   // (64 j-tiles, 64 m-tiles); j fastest -> A-tile L2 reuse
    onlstm_kernel<<<grid, NTHREADS, SMEM_BYTES>>>(cx, bih, bhh, out_hy, out_cy);
}

// round 15
// speedup vs baseline: 1.1175x; 1.1175x over previous
#include <cuda_runtime.h>
#include <cuda_fp16.h>
#include <cstdint>
#include <cstddef>

// ---------------- problem constants ----------------
#define B_DIM   8192
#define H_DIM   1024
#define NC_DIM  16
#define KTOT    2048          // IN + H

// ---------------- tile config ----------------
#define BM      128
#define BN      64            // 4 gates x 16 (gate-interleaved)
#define BK      64            // 64 fp16 = 128 bytes per row (one SW128 row)
#define STAGES  3
#define NKIT    (KTOT / BK)   // 32
#define NTHREADS 128          // 4 warps, warp tile 64x32

// SMEM layout
#define SM_TILES   1024                          // stage buffers start
#define SA_BYTES   (BM * 128)                    // 16384
#define SB_BYTES   (BN * 128)                    // 8192
#define SSTRIDE    (SA_BYTES + SB_BYTES)         // 24576
#define SMEM_BYTES (SM_TILES + STAGES * SSTRIDE) // 74752 (x3 CTAs = 224256 <= 228KB)

#define EPI_PITCH  68                            // fp32 epilogue staging pitch (mult of 4)

// ---------------- device scratch ----------------
__device__ __align__(16) __half g_A[(size_t)B_DIM * KTOT];      // [x | hx]
__device__ __align__(16) __half g_B[(size_t)4 * H_DIM * KTOT];  // [W_ih | W_hh]
__device__ float g_cin[B_DIM * NC_DIM];
__device__ float g_cfg[B_DIM * NC_DIM];

// ---------------- helpers ----------------
__device__ __forceinline__ uint32_t smem_u32(const void* p) {
    uint32_t a;
    asm("{ .reg .u64 t; cvta.to.shared.u64 t, %1; cvt.u32.u64 %0, t; }" : "=r"(a) : "l"(p));
    return a;
}

__device__ __forceinline__ uint32_t sw128(uint32_t off) { return off ^ ((off >> 3) & 0x70); }

__device__ __forceinline__ void cp_async16(uint32_t dst, const void* src) {
    asm volatile("cp.async.cg.shared.global [%0], [%1], 16;" :: "r"(dst), "l"(src) : "memory");
}
#define CP_COMMIT() asm volatile("cp.async.commit_group;" ::: "memory")
#define CP_WAIT(N)  asm volatile("cp.async.wait_group %0;" :: "n"(N) : "memory")

__device__ __forceinline__ void ldsm4(uint32_t* r, uint32_t addr) {
    asm volatile("ldmatrix.sync.aligned.m8n8.x4.shared.b16 {%0,%1,%2,%3}, [%4];"
                 : "=r"(r[0]), "=r"(r[1]), "=r"(r[2]), "=r"(r[3]) : "r"(addr));
}

__device__ __forceinline__ void mma16816(float* d, const uint32_t* a, const uint32_t* b) {
    asm volatile("mma.sync.aligned.m16n8k16.row.col.f32.f16.f16.f32 "
                 "{%0,%1,%2,%3}, {%4,%5,%6,%7}, {%8,%9}, {%0,%1,%2,%3};"
                 : "+f"(d[0]), "+f"(d[1]), "+f"(d[2]), "+f"(d[3])
                 : "r"(a[0]), "r"(a[1]), "r"(a[2]), "r"(a[3]), "r"(b[0]), "r"(b[1]));
}

__device__ __forceinline__ float sigmoidf_(float x) { return 1.0f / (1.0f + __expf(-x)); }

// ---------------- conversion kernels ----------------
__global__ void convA_kernel(const float* __restrict__ x, const float* __restrict__ hx) {
    size_t i = ((size_t)blockIdx.x * blockDim.x + threadIdx.x) * 8;
    int b = (int)(i >> 11);
    int k = (int)(i & 2047);
    const float* src = (k < 1024) ? (x + (size_t)b * 1024 + k)
                                  : (hx + (size_t)b * 1024 + (k - 1024));
    float4 f0 = *(const float4*)src;
    float4 f1 = *(const float4*)(src + 4);
    __half2 h[4];
    h[0] = __floats2half2_rn(f0.x, f0.y);
    h[1] = __floats2half2_rn(f0.z, f0.w);
    h[2] = __floats2half2_rn(f1.x, f1.y);
    h[3] = __floats2half2_rn(f1.z, f1.w);
    *(uint4*)(g_A + i) = *(uint4*)h;
}

__global__ void convB_kernel(const float* __restrict__ Wih, const float* __restrict__ Whh) {
    size_t i = ((size_t)blockIdx.x * blockDim.x + threadIdx.x) * 8;
    int g = (int)(i >> 11);
    int k = (int)(i & 2047);
    const float* src = (k < 1024) ? (Wih + (size_t)g * 1024 + k)
                                  : (Whh + (size_t)g * 1024 + (k - 1024));
    float4 f0 = *(const float4*)src;
    float4 f1 = *(const float4*)(src + 4);
    __half2 h[4];
    h[0] = __floats2half2_rn(f0.x, f0.y);
    h[1] = __floats2half2_rn(f0.z, f0.w);
    h[2] = __floats2half2_rn(f1.x, f1.y);
    h[3] = __floats2half2_rn(f1.z, f1.w);
    *(uint4*)(g_B + i) = *(uint4*)h;
}

// ---------------- cumsoftmax floors ----------------
__global__ void floors_kernel(const float* __restrict__ ifl, const float* __restrict__ ffl) {
    int b = blockIdx.x * blockDim.x + threadIdx.x;
    if (b >= B_DIM) return;
    float v[16], w[16];
#pragma unroll
    for (int i = 0; i < 16; i++) { v[i] = ifl[b * 16 + i]; w[i] = ffl[b * 16 + i]; }
#pragma unroll
    for (int h = 0; h < 4; h++) {
        float* a = (h < 2) ? (v + 8 * h) : (w + 8 * (h - 2));
        float m = a[0];
#pragma unroll
        for (int i = 1; i < 8; i++) m = fmaxf(m, a[i]);
        float s = 0.f;
#pragma unroll
        for (int i = 0; i < 8; i++) { a[i] = expf(a[i] - m); s += a[i]; }
        float inv = 1.0f / s;
#pragma unroll
        for (int i = 0; i < 8; i++) a[i] *= inv;
    }
    float* cin = g_cin + (size_t)b * 16;
    float* cfg = g_cfg + (size_t)b * 16;
    float run;
    run = 0.f;
#pragma unroll
    for (int i = 0; i < 8; i++) { run += v[i]; cin[i] = run; }          // happy in: prefix
    run = 0.f;
#pragma unroll
    for (int i = 7; i >= 0; i--) { run += v[8 + i]; cin[8 + i] = run; } // sad in: suffix
    run = 0.f;
#pragma unroll
    for (int i = 7; i >= 0; i--) { run += w[i]; cfg[i] = run; }         // happy fg: suffix
    run = 0.f;
#pragma unroll
    for (int i = 0; i < 8; i++) { run += w[8 + i]; cfg[8 + i] = run; }  // sad fg: prefix
}

// ---------------- linear-address stage loader ----------------
// Thread tid owns A rows r0, r0+16, ..., r0+112 (chunk column c0) and
// B rows r0, r0+16, r0+32, r0+48 (gates 0..3, col j*16 + r0's lane).
// All addresses are base + constant: swizzle bits [7:9] depend only on r0.
__device__ __forceinline__ void load_stage_lin(
    uint32_t abase, uint32_t bbase, uint32_t offd,
    const __half* sA, const __half* sB)
{
#pragma unroll
    for (int i = 0; i < 8; i++)
        cp_async16(abase + offd + i * 2048, sA + (size_t)i * 16 * KTOT);
#pragma unroll
    for (int m = 0; m < 4; m++)
        cp_async16(bbase + offd + m * 2048, sB + (size_t)m * 1024 * KTOT);
}

// ---------------- fused GEMM + ONLSTM epilogue ----------------
__global__ void __launch_bounds__(NTHREADS, 3)
onlstm_kernel(const float* __restrict__ cx,
              const float* __restrict__ bih, const float* __restrict__ bhh,
              float* __restrict__ out_hy, float* __restrict__ out_cy)
{
    extern __shared__ char smem[];
    const int tid = threadIdx.x;
    const int wid = tid >> 5, lane = tid & 31;
    const int j  = blockIdx.x;          // 16-column tile index 0..63
    const int m0 = blockIdx.y * BM;     // batch-row base
    const uint32_t sb = smem_u32(smem);

    float* sbias = (float*)smem;        // 64 floats, region [0,1024)
    if (tid < 64) {
        int grow = (tid >> 4) * 1024 + j * 16 + (tid & 15);
        sbias[tid] = bih[grow] + bhh[grow];
    }

    // per-thread linear load bases (computed once)
    const int r0 = tid >> 3, c0 = tid & 7;
    const __half* sA0 = g_A + (size_t)(m0 + r0) * KTOT + c0 * 8;
    const __half* sB0 = g_B + (size_t)(j * 16 + r0) * KTOT + c0 * 8;
    const uint32_t offd = sw128((uint32_t)(r0 * 128 + c0 * 16));
    const uint32_t tbase = sb + SM_TILES;

    // prologue: prefetch stages 0..1
#pragma unroll
    for (int p = 0; p < STAGES - 1; p++) {
        load_stage_lin(tbase + p * SSTRIDE, tbase + p * SSTRIDE + SA_BYTES,
                       offd, sA0 + p * BK, sB0 + p * BK);
        CP_COMMIT();
    }

    const int wm = wid >> 1;            // 0..1  (M)
    const int wn = wid & 1;             // 0..1  (N)

    float acc[4][4][4];                 // 64x32 warp tile: 4 m16 x 4 n8
#pragma unroll
    for (int i = 0; i < 4; i++)
#pragma unroll
        for (int jn = 0; jn < 4; jn++)
#pragma unroll
            for (int t = 0; t < 4; t++) acc[i][jn][t] = 0.f;

    int buf = 0;
    for (int s = 0; s < NKIT; s++) {
        CP_WAIT(STAGES - 2);            // stage s data landed
        __syncthreads();                // all warps done computing stage s-1

        // issue stage s+2 loads FIRST (into buf of stage s-1) — cheap, 2-stage lookahead
        const int ps = s + STAGES - 1;
        if (ps < NKIT) {
            int pbuf = buf + (STAGES - 1);
            if (pbuf >= STAGES) pbuf -= STAGES;
            uint32_t ab2 = tbase + pbuf * SSTRIDE;
            load_stage_lin(ab2, ab2 + SA_BYTES, offd, sA0 + ps * BK, sB0 + ps * BK);
        }
        CP_COMMIT();

        const uint32_t ab = tbase + buf * SSTRIDE;
        const uint32_t bb = ab + SA_BYTES;

#pragma unroll
        for (int ks = 0; ks < 4; ks++) {        // 4 x k16 steps per stage
            uint32_t a_regs[4][4], b_regs[2][4];
#pragma unroll
            for (int i = 0; i < 4; i++) {
                int m  = wm * 64 + i * 16 + (lane & 15);
                int kc = ks * 2 + (lane >> 4);
                ldsm4(a_regs[i], ab + sw128((uint32_t)(m * 128 + kc * 16)));
            }
#pragma unroll
            for (int p = 0; p < 2; p++) {
                int n  = wn * 32 + p * 16 + ((lane >> 4) & 1) * 8 + (lane & 7);
                int kc = ks * 2 + ((lane >> 3) & 1);
                ldsm4(b_regs[p], bb + sw128((uint32_t)(n * 128 + kc * 16)));
            }
#pragma unroll
            for (int i = 0; i < 4; i++)
#pragma unroll
                for (int jn = 0; jn < 4; jn++)
                    mma16816(acc[i][jn], a_regs[i], &b_regs[jn >> 1][(jn & 1) * 2]);
        }

        if (++buf == STAGES) buf = 0;
    }

    __syncthreads();

    // stage accumulators (raw gates, no bias yet) into SMEM, overlaying tile buffers
    float* epi = (float*)(smem + SM_TILES);
#pragma unroll
    for (int i = 0; i < 4; i++) {
#pragma unroll
        for (int jn = 0; jn < 4; jn++) {
            int r = wm * 64 + i * 16 + (lane >> 2);
            int c = wn * 32 + jn * 8 + (lane & 3) * 2;
            *(float2*)&epi[r * EPI_PITCH + c]       = make_float2(acc[i][jn][0], acc[i][jn][1]);
            *(float2*)&epi[(r + 8) * EPI_PITCH + c] = make_float2(acc[i][jn][2], acc[i][jn][3]);
        }
    }
    __syncthreads();

    // fused ONLSTM epilogue: this CTA owns gate columns [j*16, j*16+16) of each gate.
    // 128 rows x 16 cols = 2048 floats = 512 float4 groups; 4 groups per row.
    const int nc = j >> 2;              // head-chunk index (16-col tile -> 64-col chunk)
#pragma unroll
    for (int t = 0; t < 4; t++) {
        int idx = tid + t * NTHREADS;      // 0..511
        int r = idx >> 2;                  // 0..127
        int c4 = (idx & 3) * 4;            // 0,4,8,12
        int b = m0 + r;
        float ci = g_cin[b * 16 + nc];
        float cf = g_cfg[b * 16 + nc];
        float ov = cf * ci;
        float fa = cf - ov, ia = ci - ov;
        float4 go = *(float4*)&epi[r * EPI_PITCH + c4];
        float4 gc = *(float4*)&epi[r * EPI_PITCH + 16 + c4];
        float4 gi = *(float4*)&epi[r * EPI_PITCH + 32 + c4];
        float4 gf = *(float4*)&epi[r * EPI_PITCH + 48 + c4];
        size_t g = (size_t)b * H_DIM + j * 16 + c4;
        float4 cxv = *(const float4*)&cx[g];
        float4 hyv, cyv;
        {
            float o  = sigmoidf_(go.x + sbias[c4]);
            float ce = tanhf    (gc.x + sbias[16 + c4]);
            float ig = sigmoidf_(gi.x + sbias[32 + c4]) * ov + ia;
            float fg = sigmoidf_(gf.x + sbias[48 + c4]) * ov + fa;
            cyv.x = fg * cxv.x + ig * ce; hyv.x = o * tanhf(cyv.x);
        }
        {
            float o  = sigmoidf_(go.y + sbias[c4 + 1]);
            float ce = tanhf    (gc.y + sbias[17 + c4]);
            float ig = sigmoidf_(gi.y + sbias[33 + c4]) * ov + ia;
            float fg = sigmoidf_(gf.y + sbias[49 + c4]) * ov + fa;
            cyv.y = fg * cxv.y + ig * ce; hyv.y = o * tanhf(cyv.y);
        }
        {
            float o  = sigmoidf_(go.z + sbias[c4 + 2]);
            float ce = tanhf    (gc.z + sbias[18 + c4]);
            float ig = sigmoidf_(gi.z + sbias[34 + c4]) * ov + ia;
            float fg = sigmoidf_(gf.z + sbias[50 + c4]) * ov + fa;
            cyv.z = fg * cxv.z + ig * ce; hyv.z = o * tanhf(cyv.z);
        }
        {
            float o  = sigmoidf_(go.w + sbias[c4 + 3]);
            float ce = tanhf    (gc.w + sbias[19 + c4]);
            float ig = sigmoidf_(gi.w + sbias[35 + c4]) * ov + ia;
            float fg = sigmoidf_(gf.w + sbias[51 + c4]) * ov + fa;
            cyv.w = fg * cxv.w + ig * ce; hyv.w = o * tanhf(cyv.w);
        }
        *(float4*)&out_hy[g] = hyv;
        if (out_cy) *(float4*)&out_cy[g] = cyv;
    }
}

// ---------------- launch ----------------
extern "C" void kernel_launch(void* const* d_in, const int* in_sizes, int n_in,
                              void* d_out, int out_size) {
    const float* x   = (const float*)d_in[0];
    const float* hx  = (const float*)d_in[1];
    const float* cx  = (const float*)d_in[2];
    const float* ifl = (const float*)d_in[3];
    const float* ffl = (const float*)d_in[4];
    const float* Wih = (const float*)d_in[5];
    const float* bih = (const float*)d_in[6];
    const float* Whh = (const float*)d_in[7];
    const float* bhh = (const float*)d_in[8];

    float* out = (float*)d_out;
    float* out_hy = out;
    float* out_cy = ((long long)out_size >= 2LL * B_DIM * H_DIM)
                        ? out + (size_t)B_DIM * H_DIM : nullptr;

    convA_kernel<<<(B_DIM * (size_t)KTOT / 8 + 255) / 256, 256>>>(x, hx);
    convB_kernel<<<(4 * (size_t)H_DIM * KTOT / 8 + 255) / 256, 256>>>(Wih, Whh);
    floors_kernel<<<B_DIM / 256, 256>>>(ifl, ffl);

    cudaFuncSetAttribute(onlstm_kernel,
                         cudaFuncAttributeMaxDynamicSharedMemorySize, SMEM_BYTES);

    dim3 grid(H_DIM / 16, B_DIM / BM);   // (64 j-tiles, 64 m-tiles); j fastest -> A-tile L2 reuse
    onlstm_kernel<<<grid, NTHREADS, SMEM_BYTES>>>(cx, bih, bhh, out_hy, out_cy);
}

// round 17
// speedup vs baseline: 1.1981x; 1.0722x over previous
#include <cuda_runtime.h>
#include <cuda_fp16.h>
#include <cstdint>
#include <cstddef>

// ---------------- problem constants ----------------
#define B_DIM   8192
#define H_DIM   1024
#define NC_DIM  16
#define KTOT    2048          // IN + H

// ---------------- tile config ----------------
#define BM      128
#define BN      64            // 4 gates x 16 (gate-interleaved)
#define BK      64            // 64 fp16 = 128 bytes per row (one SW128 row)
#define STAGES  2
#define NKIT    (KTOT / BK)   // 32
#define NTHREADS 128          // 4 warps, warp tile 64x32

// SMEM layout
#define SM_TILES   1024                          // stage buffers start
#define SA_BYTES   (BM * 128)                    // 16384
#define SB_BYTES   (BN * 128)                    // 8192
#define SSTRIDE    (SA_BYTES + SB_BYTES)         // 24576
#define SMEM_BYTES (SM_TILES + STAGES * SSTRIDE) // 50176 (x4 CTAs = 200704 <= 227KB)

#define EPI_PITCH  68                            // fp32 epilogue staging pitch (mult of 4)

// ---------------- device scratch ----------------
__device__ __align__(16) __half g_A[(size_t)B_DIM * KTOT];      // [x | hx]
__device__ __align__(16) __half g_B[(size_t)4 * H_DIM * KTOT];  // [W_ih | W_hh]
__device__ float g_cin[B_DIM * NC_DIM];
__device__ float g_cfg[B_DIM * NC_DIM];

// ---------------- helpers ----------------
__device__ __forceinline__ uint32_t smem_u32(const void* p) {
    uint32_t a;
    asm("{ .reg .u64 t; cvta.to.shared.u64 t, %1; cvt.u32.u64 %0, t; }" : "=r"(a) : "l"(p));
    return a;
}

__device__ __forceinline__ uint32_t sw128(uint32_t off) { return off ^ ((off >> 3) & 0x70); }

__device__ __forceinline__ void cp_async16(uint32_t dst, const void* src) {
    asm volatile("cp.async.cg.shared.global [%0], [%1], 16;" :: "r"(dst), "l"(src) : "memory");
}
#define CP_COMMIT() asm volatile("cp.async.commit_group;" ::: "memory")
#define CP_WAIT(N)  asm volatile("cp.async.wait_group %0;" :: "n"(N) : "memory")

__device__ __forceinline__ void ldsm4(uint32_t* r, uint32_t addr) {
    asm volatile("ldmatrix.sync.aligned.m8n8.x4.shared.b16 {%0,%1,%2,%3}, [%4];"
                 : "=r"(r[0]), "=r"(r[1]), "=r"(r[2]), "=r"(r[3]) : "r"(addr));
}

__device__ __forceinline__ void mma16816(float* d, const uint32_t* a, const uint32_t* b) {
    asm volatile("mma.sync.aligned.m16n8k16.row.col.f32.f16.f16.f32 "
                 "{%0,%1,%2,%3}, {%4,%5,%6,%7}, {%8,%9}, {%0,%1,%2,%3};"
                 : "+f"(d[0]), "+f"(d[1]), "+f"(d[2]), "+f"(d[3])
                 : "r"(a[0]), "r"(a[1]), "r"(a[2]), "r"(a[3]), "r"(b[0]), "r"(b[1]));
}

__device__ __forceinline__ float sigmoidf_(float x) { return 1.0f / (1.0f + __expf(-x)); }

// ---------------- conversion kernels ----------------
__global__ void convA_kernel(const float* __restrict__ x, const float* __restrict__ hx) {
    size_t i = ((size_t)blockIdx.x * blockDim.x + threadIdx.x) * 8;
    int b = (int)(i >> 11);
    int k = (int)(i & 2047);
    const float* src = (k < 1024) ? (x + (size_t)b * 1024 + k)
                                  : (hx + (size_t)b * 1024 + (k - 1024));
    float4 f0 = *(const float4*)src;
    float4 f1 = *(const float4*)(src + 4);
    __half2 h[4];
    h[0] = __floats2half2_rn(f0.x, f0.y);
    h[1] = __floats2half2_rn(f0.z, f0.w);
    h[2] = __floats2half2_rn(f1.x, f1.y);
    h[3] = __floats2half2_rn(f1.z, f1.w);
    *(uint4*)(g_A + i) = *(uint4*)h;
}

__global__ void convB_kernel(const float* __restrict__ Wih, const float* __restrict__ Whh) {
    size_t i = ((size_t)blockIdx.x * blockDim.x + threadIdx.x) * 8;
    int g = (int)(i >> 11);
    int k = (int)(i & 2047);
    const float* src = (k < 1024) ? (Wih + (size_t)g * 1024 + k)
                                  : (Whh + (size_t)g * 1024 + (k - 1024));
    float4 f0 = *(const float4*)src;
    float4 f1 = *(const float4*)(src + 4);
    __half2 h[4];
    h[0] = __floats2half2_rn(f0.x, f0.y);
    h[1] = __floats2half2_rn(f0.z, f0.w);
    h[2] = __floats2half2_rn(f1.x, f1.y);
    h[3] = __floats2half2_rn(f1.z, f1.w);
    *(uint4*)(g_B + i) = *(uint4*)h;
}

// ---------------- cumsoftmax floors ----------------
__global__ void floors_kernel(const float* __restrict__ ifl, const float* __restrict__ ffl) {
    int b = blockIdx.x * blockDim.x + threadIdx.x;
    if (b >= B_DIM) return;
    float v[16], w[16];
#pragma unroll
    for (int i = 0; i < 16; i++) { v[i] = ifl[b * 16 + i]; w[i] = ffl[b * 16 + i]; }
#pragma unroll
    for (int h = 0; h < 4; h++) {
        float* a = (h < 2) ? (v + 8 * h) : (w + 8 * (h - 2));
        float m = a[0];
#pragma unroll
        for (int i = 1; i < 8; i++) m = fmaxf(m, a[i]);
        float s = 0.f;
#pragma unroll
        for (int i = 0; i < 8; i++) { a[i] = expf(a[i] - m); s += a[i]; }
        float inv = 1.0f / s;
#pragma unroll
        for (int i = 0; i < 8; i++) a[i] *= inv;
    }
    float* cin = g_cin + (size_t)b * 16;
    float* cfg = g_cfg + (size_t)b * 16;
    float run;
    run = 0.f;
#pragma unroll
    for (int i = 0; i < 8; i++) { run += v[i]; cin[i] = run; }          // happy in: prefix
    run = 0.f;
#pragma unroll
    for (int i = 7; i >= 0; i--) { run += v[8 + i]; cin[8 + i] = run; } // sad in: suffix
    run = 0.f;
#pragma unroll
    for (int i = 7; i >= 0; i--) { run += w[i]; cfg[i] = run; }         // happy fg: suffix
    run = 0.f;
#pragma unroll
    for (int i = 0; i < 8; i++) { run += w[8 + i]; cfg[8 + i] = run; }  // sad fg: prefix
}

// ---------------- linear-address stage loader ----------------
// Thread tid owns A rows r0, r0+16, ..., r0+112 (chunk column c0) and
// B rows r0, r0+16, r0+32, r0+48 (gates 0..3, col j*16 + r0's lane).
// All addresses are base + constant: swizzle bits [7:9] depend only on r0.
__device__ __forceinline__ void load_stage_lin(
    uint32_t abase, uint32_t bbase, uint32_t offd,
    const __half* sA, const __half* sB)
{
#pragma unroll
    for (int i = 0; i < 8; i++)
        cp_async16(abase + offd + i * 2048, sA + (size_t)i * 16 * KTOT);
#pragma unroll
    for (int m = 0; m < 4; m++)
        cp_async16(bbase + offd + m * 2048, sB + (size_t)m * 1024 * KTOT);
}

// ---------------- fused GEMM + ONLSTM epilogue ----------------
__global__ void __launch_bounds__(NTHREADS, 4)
onlstm_kernel(const float* __restrict__ cx,
              const float* __restrict__ bih, const float* __restrict__ bhh,
              float* __restrict__ out_hy, float* __restrict__ out_cy)
{
    extern __shared__ char smem[];
    const int tid = threadIdx.x;
    const int wid = tid >> 5, lane = tid & 31;
    const int j  = blockIdx.x;          // 16-column tile index 0..63
    const int m0 = blockIdx.y * BM;     // batch-row base
    const uint32_t sb = smem_u32(smem);

    float* sbias = (float*)smem;        // 64 floats, region [0,1024)
    if (tid < 64) {
        int grow = (tid >> 4) * 1024 + j * 16 + (tid & 15);
        sbias[tid] = bih[grow] + bhh[grow];
    }

    // per-thread linear load bases (computed once)
    const int r0 = tid >> 3, c0 = tid & 7;
    const __half* sA0 = g_A + (size_t)(m0 + r0) * KTOT + c0 * 8;
    const __half* sB0 = g_B + (size_t)(j * 16 + r0) * KTOT + c0 * 8;
    const uint32_t offd = sw128((uint32_t)(r0 * 128 + c0 * 16));
    const uint32_t tbase = sb + SM_TILES;

    // prologue: prefetch stage 0
    load_stage_lin(tbase, tbase + SA_BYTES, offd, sA0, sB0);
    CP_COMMIT();

    const int wm = wid >> 1;            // 0..1  (M)
    const int wn = wid & 1;             // 0..1  (N)

    float acc[4][4][4];                 // 64x32 warp tile: 4 m16 x 4 n8
#pragma unroll
    for (int i = 0; i < 4; i++)
#pragma unroll
        for (int jn = 0; jn < 4; jn++)
#pragma unroll
            for (int t = 0; t < 4; t++) acc[i][jn][t] = 0.f;

    int buf = 0;
    for (int s = 0; s < NKIT; s++) {
        CP_WAIT(0);                     // stage s data landed (own copies)
        __syncthreads();                // visibility + all warps done with buf^1

        // issue stage s+1 into buf^1 — flat cp.asyncs, no address math
        if (s + 1 < NKIT) {
            uint32_t ab2 = tbase + (buf ^ 1) * SSTRIDE;
            load_stage_lin(ab2, ab2 + SA_BYTES, offd,
                           sA0 + (s + 1) * BK, sB0 + (s + 1) * BK);
        }
        CP_COMMIT();

        const uint32_t ab = tbase + buf * SSTRIDE;
        const uint32_t bb = ab + SA_BYTES;

#pragma unroll
        for (int ks = 0; ks < 4; ks++) {        // 4 x k16 steps per stage
            uint32_t a_regs[4][4], b_regs[2][4];
#pragma unroll
            for (int i = 0; i < 4; i++) {
                int m  = wm * 64 + i * 16 + (lane & 15);
                int kc = ks * 2 + (lane >> 4);
                ldsm4(a_regs[i], ab + sw128((uint32_t)(m * 128 + kc * 16)));
            }
#pragma unroll
            for (int p = 0; p < 2; p++) {
                int n  = wn * 32 + p * 16 + ((lane >> 4) & 1) * 8 + (lane & 7);
                int kc = ks * 2 + ((lane >> 3) & 1);
                ldsm4(b_regs[p], bb + sw128((uint32_t)(n * 128 + kc * 16)));
            }
#pragma unroll
            for (int i = 0; i < 4; i++)
#pragma unroll
                for (int jn = 0; jn < 4; jn++)
                    mma16816(acc[i][jn], a_regs[i], &b_regs[jn >> 1][(jn & 1) * 2]);
        }

        buf ^= 1;
    }

    __syncthreads();

    // stage accumulators (raw gates, no bias yet) into SMEM, overlaying tile buffers
    float* epi = (float*)(smem + SM_TILES);
#pragma unroll
    for (int i = 0; i < 4; i++) {
#pragma unroll
        for (int jn = 0; jn < 4; jn++) {
            int r = wm * 64 + i * 16 + (lane >> 2);
            int c = wn * 32 + jn * 8 + (lane & 3) * 2;
            *(float2*)&epi[r * EPI_PITCH + c]       = make_float2(acc[i][jn][0], acc[i][jn][1]);
            *(float2*)&epi[(r + 8) * EPI_PITCH + c] = make_float2(acc[i][jn][2], acc[i][jn][3]);
        }
    }
    __syncthreads();

    // fused ONLSTM epilogue: this CTA owns gate columns [j*16, j*16+16) of each gate.
    // 128 rows x 16 cols = 2048 floats = 512 float4 groups; 4 groups per row.
    const int nc = j >> 2;              // head-chunk index (16-col tile -> 64-col chunk)
#pragma unroll
    for (int t = 0; t < 4; t++) {
        int idx = tid + t * NTHREADS;      // 0..511
        int r = idx >> 2;                  // 0..127
        int c4 = (idx & 3) * 4;            // 0,4,8,12
        int b = m0 + r;
        float ci = g_cin[b * 16 + nc];
        float cf = g_cfg[b * 16 + nc];
        float ov = cf * ci;
        float fa = cf - ov, ia = ci - ov;
        float4 go = *(float4*)&epi[r * EPI_PITCH + c4];
        float4 gc = *(float4*)&epi[r * EPI_PITCH + 16 + c4];
        float4 gi = *(float4*)&epi[r * EPI_PITCH + 32 + c4];
        float4 gf = *(float4*)&epi[r * EPI_PITCH + 48 + c4];
        size_t g = (size_t)b * H_DIM + j * 16 + c4;
        float4 cxv = *(const float4*)&cx[g];
        float4 hyv, cyv;
        {
            float o  = sigmoidf_(go.x + sbias[c4]);
            float ce = tanhf    (gc.x + sbias[16 + c4]);
            float ig = sigmoidf_(gi.x + sbias[32 + c4]) * ov + ia;
            float fg = sigmoidf_(gf.x + sbias[48 + c4]) * ov + fa;
            cyv.x = fg * cxv.x + ig * ce; hyv.x = o * tanhf(cyv.x);
        }
        {
            float o  = sigmoidf_(go.y + sbias[c4 + 1]);
            float ce = tanhf    (gc.y + sbias[17 + c4]);
            float ig = sigmoidf_(gi.y + sbias[33 + c4]) * ov + ia;
            float fg = sigmoidf_(gf.y + sbias[49 + c4]) * ov + fa;
            cyv.y = fg * cxv.y + ig * ce; hyv.y = o * tanhf(cyv.y);
        }
        {
            float o  = sigmoidf_(go.z + sbias[c4 + 2]);
            float ce = tanhf    (gc.z + sbias[18 + c4]);
            float ig = sigmoidf_(gi.z + sbias[34 + c4]) * ov + ia;
            float fg = sigmoidf_(gf.z + sbias[50 + c4]) * ov + fa;
            cyv.z = fg * cxv.z + ig * ce; hyv.z = o * tanhf(cyv.z);
        }
        {
            float o  = sigmoidf_(go.w + sbias[c4 + 3]);
            float ce = tanhf    (gc.w + sbias[19 + c4]);
            float ig = sigmoidf_(gi.w + sbias[35 + c4]) * ov + ia;
            float fg = sigmoidf_(gf.w + sbias[51 + c4]) * ov + fa;
            cyv.w = fg * cxv.w + ig * ce; hyv.w = o * tanhf(cyv.w);
        }
        *(float4*)&out_hy[g] = hyv;
        if (out_cy) *(float4*)&out_cy[g] = cyv;
    }
}

// ---------------- launch ----------------
extern "C" void kernel_launch(void* const* d_in, const int* in_sizes, int n_in,
                              void* d_out, int out_size) {
    const float* x   = (const float*)d_in[0];
    const float* hx  = (const float*)d_in[1];
    const float* cx  = (const float*)d_in[2];
    const float* ifl = (const float*)d_in[3];
    const float* ffl = (const float*)d_in[4];
    const float* Wih = (const float*)d_in[5];
    const float* bih = (const float*)d_in[6];
    const float* Whh = (const float*)d_in[7];
    const float* bhh = (const float*)d_in[8];

    float* out = (float*)d_out;
    float* out_hy = out;
    float* out_cy = ((long long)out_size >= 2LL * B_DIM * H_DIM)
                        ? out + (size_t)B_DIM * H_DIM : nullptr;

    convA_kernel<<<(B_DIM * (size_t)KTOT / 8 + 255) / 256, 256>>>(x, hx);
    convB_kernel<<<(4 * (size_t)H_DIM * KTOT / 8 + 255) / 256, 256>>>(Wih, Whh);
    floors_kernel<<<B_DIM / 256, 256>>>(ifl, ffl);

    cudaFuncSetAttribute(onlstm_kernel,
                         cudaFuncAttributeMaxDynamicSharedMemorySize, SMEM_BYTES);

    dim3 grid(H_DIM / 16, B_DIM / BM);   // (64 j-tiles, 64 m-tiles); j fastest -> A-tile L2 reuse
    onlstm_kernel<<<grid, NTHREADS, SMEM_BYTES>>>(cx, bih, bhh, out_hy, out_cy);
}